// round 11
// baseline (speedup 1.0000x reference)
#include <cuda_runtime.h>
#include <cstddef>

// Pixel_RNNcontrol: h_t = tanh(x_t @ W_ih^T + h_{t-1} @ W_hh^T + b), out = sigmoid(10 h_t)
// T=128, B=262144, I=H=2.
//
// R11: one batch element per thread (float2) -> 8192 warps (2x prior), the one
// untested axis: all float4 configs pinned occupancy at ~40% / DRAM ~74%.
// Doubling independent request streams should lift DRAM toward its mixed-stream
// ceiling. tanh prescale (2*log2e) folded into weights/bias: z computed in the
// scaled domain directly (h unchanged -> numerically identical recurrence).
// Loop structure from R10 (unconditional main, predicated cleanup, tail).

#define PF  4
#define TPB 256

// h = tanh(z) computed from k = 2*log2(e)*z  (k supplied pre-scaled)
__device__ __forceinline__ float tanh_scaled(float k) {
    float e;
    asm("ex2.approx.f32 %0, %1;" : "=f"(e) : "f"(k));   // e^{2z}
    float r;
    float d = e + 1.0f;
    asm("rcp.approx.f32 %0, %1;" : "=f"(r) : "f"(d));
    return fmaf(-2.0f, r, 1.0f);
}

__device__ __forceinline__ float sig10(float h) {
    // sigmoid(10h) = 0.5 + 0.5*tanh(5h); HW tanh -> 1 MUFU, error non-accumulating
    float t;
    float a = 5.0f * h;
    asm("tanh.approx.f32 %0, %1;" : "=f"(t) : "f"(a));
    return fmaf(0.5f, t, 0.5f);
}

__global__ void __launch_bounds__(TPB)
rnn_sigmoid_kernel(const float2* __restrict__ x2,
                   const float2* __restrict__ h02,
                   const float*  __restrict__ Wih,
                   const float*  __restrict__ Whh,
                   const float*  __restrict__ bih,
                   const float*  __restrict__ bhh,
                   float2* __restrict__ out2,
                   float2* __restrict__ hout2,
                   int T, int B)
{
    int p = blockIdx.x * TPB + threadIdx.x;
    if (p >= B) return;

    // Fold the tanh input prescale S = 2*log2(e) into weights and bias:
    // k = S*z = (S*W)x + (S*U)h + S*b; h = tanh_scaled(k) is exactly tanh(z).
    const float S = 2.885390082f;
    const float a00 = S * Wih[0], a01 = S * Wih[1], a10 = S * Wih[2], a11 = S * Wih[3];
    const float w00 = S * Whh[0], w01 = S * Whh[1], w10 = S * Whh[2], w11 = S * Whh[3];
    const float b0 = S * (bih[0] + bhh[0]);
    const float b1 = S * (bih[1] + bhh[1]);

    float2 hv = h02[p];
    float h0 = hv.x, h1 = hv.y;

    // Prime the pipeline: PF loads in flight before the loop.
    float2 buf[PF];
    #pragma unroll
    for (int i = 0; i < PF; ++i) {
        int ti = (i < T) ? i : (T - 1);
        buf[i] = __ldcs(&x2[(size_t)ti * B + p]);
    }

    const float2* xld = x2 + (size_t)PF * B + p;   // next load addr (t = PF)
    float2*       ost = out2 + p;                   // store addr (t = 0)
    const size_t  stride = (size_t)B;

    int t = 0;

    // Main loop: all PF prefetch loads guaranteed in-range (t + 2*PF <= T).
    for (; t + 2 * PF <= T; t += PF) {
        #pragma unroll
        for (int i = 0; i < PF; ++i) {
            float2 xv = buf[i];
            buf[i] = __ldcs(&xld[(size_t)i * stride]);   // unconditional

            float k0 = fmaf(a00, xv.x, fmaf(a01, xv.y, fmaf(w00, h0, fmaf(w01, h1, b0))));
            float k1 = fmaf(a10, xv.x, fmaf(a11, xv.y, fmaf(w10, h0, fmaf(w11, h1, b1))));

            h0 = tanh_scaled(k0);
            h1 = tanh_scaled(k1);

            float2 o;
            o.x = sig10(h0);
            o.y = sig10(h1);
            __stcs(&ost[(size_t)i * stride], o);
        }
        xld += (size_t)PF * stride;
        ost += (size_t)PF * stride;
    }

    // Cleanup groups: predicated loads.
    for (; t + PF <= T; t += PF) {
        #pragma unroll
        for (int i = 0; i < PF; ++i) {
            float2 xv = buf[i];
            if (t + i + PF < T) buf[i] = __ldcs(&xld[(size_t)i * stride]);

            float k0 = fmaf(a00, xv.x, fmaf(a01, xv.y, fmaf(w00, h0, fmaf(w01, h1, b0))));
            float k1 = fmaf(a10, xv.x, fmaf(a11, xv.y, fmaf(w10, h0, fmaf(w11, h1, b1))));

            h0 = tanh_scaled(k0);
            h1 = tanh_scaled(k1);

            float2 o;
            o.x = sig10(h0);
            o.y = sig10(h1);
            __stcs(&ost[(size_t)i * stride], o);
        }
        xld += (size_t)PF * stride;
        ost += (size_t)PF * stride;
    }

    // Scalar tail (T % PF != 0).
    for (int i = 0; t < T; ++t, ++i) {
        float2 xv = buf[i];
        float k0 = fmaf(a00, xv.x, fmaf(a01, xv.y, fmaf(w00, h0, fmaf(w01, h1, b0))));
        float k1 = fmaf(a10, xv.x, fmaf(a11, xv.y, fmaf(w10, h0, fmaf(w11, h1, b1))));
        h0 = tanh_scaled(k0);
        h1 = tanh_scaled(k1);
        float2 o;
        o.x = sig10(h0);
        o.y = sig10(h1);
        __stcs(&ost[(size_t)i * stride], o);
    }

    float2 hf;
    hf.x = h0; hf.y = h1;
    hout2[p] = hf;
}

extern "C" void kernel_launch(void* const* d_in, const int* in_sizes, int n_in,
                              void* d_out, int out_size)
{
    const float* x   = (const float*)d_in[0];   // (T, B, 2)
    const float* h0  = (const float*)d_in[1];   // (1, B, 2)
    const float* Wih = (const float*)d_in[2];   // (2, 2)
    const float* Whh = (const float*)d_in[3];   // (2, 2)
    const float* bih = (const float*)d_in[4];   // (2,)
    const float* bhh = (const float*)d_in[5];   // (2,)

    const int BH = in_sizes[1];                 // B * H = B * 2
    const int B  = BH / 2;
    const int T  = in_sizes[0] / BH;            // (T*B*2) / (B*2)

    float* out = (float*)d_out;                 // first T*B*2 elems: out
    float* hout = out + ((size_t)out_size - (size_t)BH);  // last B*2 elems: hidden

    const int blocks = (B + TPB - 1) / TPB;

    rnn_sigmoid_kernel<<<blocks, TPB>>>(
        (const float2*)x, (const float2*)h0,
        Wih, Whh, bih, bhh,
        (float2*)out, (float2*)hout,
        T, B);
}

// round 12
// speedup vs baseline: 1.1381x; 1.1381x over previous
#include <cuda_runtime.h>
#include <cstddef>

// Pixel_RNNcontrol: h_t = tanh(x_t @ W_ih^T + h_{t-1} @ W_hh^T + b), out = sigmoid(10 h_t)
// T=128, B=262144, I=H=2. One thread handles 2 batch elements (float4 lanes).
//
// R12: exact R10 structure (best: 90.2us wall / 85.3 ncu / DRAM 74.1%) with ONE
// change: stores use default .wb instead of .cs. Theory: evict-first on stores
// causes partial-line (sub-128B) writebacks before L2 aggregates all sectors;
// .wb lets L2 emit full-line writebacks. Loads keep .cs (x has zero reuse).

#define PF 4   // prefetch depth

__device__ __forceinline__ float exact_tanh(float z) {
    // tanh(z) = 1 - 2/(1 + e^{2z}); z bounded (|z| <~ 7) -> no overflow
    float k = 2.885390082f * z;        // 2*log2(e) * z
    float e;
    asm("ex2.approx.f32 %0, %1;" : "=f"(e) : "f"(k));
    float r;
    float d = e + 1.0f;
    asm("rcp.approx.f32 %0, %1;" : "=f"(r) : "f"(d));
    return fmaf(-2.0f, r, 1.0f);
}

__device__ __forceinline__ float sig10(float h) {
    // sigmoid(10h) = 0.5 + 0.5*tanh(5h); HW tanh -> 1 MUFU, error non-accumulating
    float t;
    float a = 5.0f * h;
    asm("tanh.approx.f32 %0, %1;" : "=f"(t) : "f"(a));
    return fmaf(0.5f, t, 0.5f);
}

__global__ void __launch_bounds__(256, 4)
rnn_sigmoid_kernel(const float4* __restrict__ x4,
                   const float4* __restrict__ h04,
                   const float*  __restrict__ Wih,
                   const float*  __restrict__ Whh,
                   const float*  __restrict__ bih,
                   const float*  __restrict__ bhh,
                   float4* __restrict__ out4,
                   float4* __restrict__ hout4,
                   int T, int npairs)
{
    int p = blockIdx.x * blockDim.x + threadIdx.x;
    if (p >= npairs) return;

    // 2x2 weights (row-major). z = x @ W^T  ->  z0 = W[0][0]*x0 + W[0][1]*x1
    const float a00 = Wih[0], a01 = Wih[1], a10 = Wih[2], a11 = Wih[3];
    const float w00 = Whh[0], w01 = Whh[1], w10 = Whh[2], w11 = Whh[3];
    const float b0 = bih[0] + bhh[0];
    const float b1 = bih[1] + bhh[1];

    float4 hv = h04[p];
    float hA0 = hv.x, hA1 = hv.y;   // batch element A
    float hB0 = hv.z, hB1 = hv.w;   // batch element B

    // Prime the pipeline: PF loads in flight before the loop.
    float4 buf[PF];
    #pragma unroll
    for (int i = 0; i < PF; ++i) {
        int ti = (i < T) ? i : (T - 1);
        buf[i] = __ldcs(&x4[(size_t)ti * npairs + p]);
    }

    const float4* xld = x4 + (size_t)PF * npairs + p;   // next load addr (t = PF)
    float4*       ost = out4 + p;                        // store addr (t = 0)
    const size_t  stride = (size_t)npairs;

    int t = 0;

    // Main loop: all PF prefetch loads guaranteed in-range (t + 2*PF <= T).
    for (; t + 2 * PF <= T; t += PF) {
        #pragma unroll
        for (int i = 0; i < PF; ++i) {
            float4 xv = buf[i];
            buf[i] = __ldcs(&xld[(size_t)i * stride]);   // unconditional

            float zA0 = fmaf(a00, xv.x, fmaf(a01, xv.y, fmaf(w00, hA0, fmaf(w01, hA1, b0))));
            float zA1 = fmaf(a10, xv.x, fmaf(a11, xv.y, fmaf(w10, hA0, fmaf(w11, hA1, b1))));
            float zB0 = fmaf(a00, xv.z, fmaf(a01, xv.w, fmaf(w00, hB0, fmaf(w01, hB1, b0))));
            float zB1 = fmaf(a10, xv.z, fmaf(a11, xv.w, fmaf(w10, hB0, fmaf(w11, hB1, b1))));

            hA0 = exact_tanh(zA0);
            hA1 = exact_tanh(zA1);
            hB0 = exact_tanh(zB0);
            hB1 = exact_tanh(zB1);

            float4 o;
            o.x = sig10(hA0);
            o.y = sig10(hA1);
            o.z = sig10(hB0);
            o.w = sig10(hB1);
            ost[(size_t)i * stride] = o;                 // .wb default
        }
        xld += (size_t)PF * stride;
        ost += (size_t)PF * stride;
    }

    // Cleanup groups: predicated loads.
    for (; t + PF <= T; t += PF) {
        #pragma unroll
        for (int i = 0; i < PF; ++i) {
            float4 xv = buf[i];
            if (t + i + PF < T) buf[i] = __ldcs(&xld[(size_t)i * stride]);

            float zA0 = fmaf(a00, xv.x, fmaf(a01, xv.y, fmaf(w00, hA0, fmaf(w01, hA1, b0))));
            float zA1 = fmaf(a10, xv.x, fmaf(a11, xv.y, fmaf(w10, hA0, fmaf(w11, hA1, b1))));
            float zB0 = fmaf(a00, xv.z, fmaf(a01, xv.w, fmaf(w00, hB0, fmaf(w01, hB1, b0))));
            float zB1 = fmaf(a10, xv.z, fmaf(a11, xv.w, fmaf(w10, hB0, fmaf(w11, hB1, b1))));

            hA0 = exact_tanh(zA0);
            hA1 = exact_tanh(zA1);
            hB0 = exact_tanh(zB0);
            hB1 = exact_tanh(zB1);

            float4 o;
            o.x = sig10(hA0);
            o.y = sig10(hA1);
            o.z = sig10(hB0);
            o.w = sig10(hB1);
            ost[(size_t)i * stride] = o;                 // .wb default
        }
        xld += (size_t)PF * stride;
        ost += (size_t)PF * stride;
    }

    // Scalar tail (T % PF != 0).
    for (int i = 0; t < T; ++t, ++i) {
        float4 xv = buf[i];
        float zA0 = fmaf(a00, xv.x, fmaf(a01, xv.y, fmaf(w00, hA0, fmaf(w01, hA1, b0))));
        float zA1 = fmaf(a10, xv.x, fmaf(a11, xv.y, fmaf(w10, hA0, fmaf(w11, hA1, b1))));
        float zB0 = fmaf(a00, xv.z, fmaf(a01, xv.w, fmaf(w00, hB0, fmaf(w01, hB1, b0))));
        float zB1 = fmaf(a10, xv.z, fmaf(a11, xv.w, fmaf(w10, hB0, fmaf(w11, hB1, b1))));
        hA0 = exact_tanh(zA0);
        hA1 = exact_tanh(zA1);
        hB0 = exact_tanh(zB0);
        hB1 = exact_tanh(zB1);
        float4 o;
        o.x = sig10(hA0); o.y = sig10(hA1); o.z = sig10(hB0); o.w = sig10(hB1);
        ost[(size_t)i * stride] = o;                     // .wb default
    }

    float4 hf;
    hf.x = hA0; hf.y = hA1; hf.z = hB0; hf.w = hB1;
    hout4[p] = hf;
}

extern "C" void kernel_launch(void* const* d_in, const int* in_sizes, int n_in,
                              void* d_out, int out_size)
{
    const float* x   = (const float*)d_in[0];   // (T, B, 2)
    const float* h0  = (const float*)d_in[1];   // (1, B, 2)
    const float* Wih = (const float*)d_in[2];   // (2, 2)
    const float* Whh = (const float*)d_in[3];   // (2, 2)
    const float* bih = (const float*)d_in[4];   // (2,)
    const float* bhh = (const float*)d_in[5];   // (2,)

    const int BH = in_sizes[1];                 // B * H = B * 2
    const int B  = BH / 2;
    const int T  = in_sizes[0] / BH;            // (T*B*2) / (B*2)

    float* out = (float*)d_out;                 // first T*B*2 elems: out
    float* hout = out + ((size_t)out_size - (size_t)BH);  // last B*2 elems: hidden

    const int npairs = B / 2;                   // float4 granularity (2 batch elems)
    const int threads = 256;
    const int blocks = (npairs + threads - 1) / threads;

    rnn_sigmoid_kernel<<<blocks, threads>>>(
        (const float4*)x, (const float4*)h0,
        Wih, Whh, bih, bhh,
        (float4*)out, (float4*)hout,
        T, npairs);
}

// round 13
// speedup vs baseline: 1.1842x; 1.0404x over previous
#include <cuda_runtime.h>
#include <cstddef>

// Pixel_RNNcontrol: h_t = tanh(x_t @ W_ih^T + h_{t-1} @ W_hh^T + b), out = sigmoid(10 h_t)
// T=128, B=262144, I=H=2. One thread handles 2 batch elements (float4 lanes).
//
// R13: R10 structure (best: 90.2us wall / DRAM 74.1%) with PF 4->3 and
// launch_bounds(256,5). At PF=4/64regs we sit exactly on the 4-CTA register
// cliff (4*256*64 = 65536 = whole RF). PF=3 fits 51 regs -> 5 CTAs/SM =
// 40 warps (+25%), and total in-flight bytes/SM actually RISES (60KB vs 51KB)
// with more independent float4 request streams. .cs on loads AND stores
// (R12 showed .wb is slightly worse).

#define PF 3   // prefetch depth

__device__ __forceinline__ float exact_tanh(float z) {
    // tanh(z) = 1 - 2/(1 + e^{2z}); z bounded (|z| <~ 7) -> no overflow
    float k = 2.885390082f * z;        // 2*log2(e) * z
    float e;
    asm("ex2.approx.f32 %0, %1;" : "=f"(e) : "f"(k));
    float r;
    float d = e + 1.0f;
    asm("rcp.approx.f32 %0, %1;" : "=f"(r) : "f"(d));
    return fmaf(-2.0f, r, 1.0f);
}

__device__ __forceinline__ float sig10(float h) {
    // sigmoid(10h) = 0.5 + 0.5*tanh(5h); HW tanh -> 1 MUFU, error non-accumulating
    float t;
    float a = 5.0f * h;
    asm("tanh.approx.f32 %0, %1;" : "=f"(t) : "f"(a));
    return fmaf(0.5f, t, 0.5f);
}

__global__ void __launch_bounds__(256, 5)
rnn_sigmoid_kernel(const float4* __restrict__ x4,
                   const float4* __restrict__ h04,
                   const float*  __restrict__ Wih,
                   const float*  __restrict__ Whh,
                   const float*  __restrict__ bih,
                   const float*  __restrict__ bhh,
                   float4* __restrict__ out4,
                   float4* __restrict__ hout4,
                   int T, int npairs)
{
    int p = blockIdx.x * blockDim.x + threadIdx.x;
    if (p >= npairs) return;

    // 2x2 weights (row-major). z = x @ W^T  ->  z0 = W[0][0]*x0 + W[0][1]*x1
    const float a00 = Wih[0], a01 = Wih[1], a10 = Wih[2], a11 = Wih[3];
    const float w00 = Whh[0], w01 = Whh[1], w10 = Whh[2], w11 = Whh[3];
    const float b0 = bih[0] + bhh[0];
    const float b1 = bih[1] + bhh[1];

    float4 hv = h04[p];
    float hA0 = hv.x, hA1 = hv.y;   // batch element A
    float hB0 = hv.z, hB1 = hv.w;   // batch element B

    // Prime the pipeline: PF loads in flight before the loop.
    float4 buf[PF];
    #pragma unroll
    for (int i = 0; i < PF; ++i) {
        int ti = (i < T) ? i : (T - 1);
        buf[i] = __ldcs(&x4[(size_t)ti * npairs + p]);
    }

    const float4* xld = x4 + (size_t)PF * npairs + p;   // next load addr (t = PF)
    float4*       ost = out4 + p;                        // store addr (t = 0)
    const size_t  stride = (size_t)npairs;

    int t = 0;

    // Main loop: all PF prefetch loads guaranteed in-range (t + 2*PF <= T).
    for (; t + 2 * PF <= T; t += PF) {
        #pragma unroll
        for (int i = 0; i < PF; ++i) {
            float4 xv = buf[i];
            buf[i] = __ldcs(&xld[(size_t)i * stride]);   // unconditional

            float zA0 = fmaf(a00, xv.x, fmaf(a01, xv.y, fmaf(w00, hA0, fmaf(w01, hA1, b0))));
            float zA1 = fmaf(a10, xv.x, fmaf(a11, xv.y, fmaf(w10, hA0, fmaf(w11, hA1, b1))));
            float zB0 = fmaf(a00, xv.z, fmaf(a01, xv.w, fmaf(w00, hB0, fmaf(w01, hB1, b0))));
            float zB1 = fmaf(a10, xv.z, fmaf(a11, xv.w, fmaf(w10, hB0, fmaf(w11, hB1, b1))));

            hA0 = exact_tanh(zA0);
            hA1 = exact_tanh(zA1);
            hB0 = exact_tanh(zB0);
            hB1 = exact_tanh(zB1);

            float4 o;
            o.x = sig10(hA0);
            o.y = sig10(hA1);
            o.z = sig10(hB0);
            o.w = sig10(hB1);
            __stcs(&ost[(size_t)i * stride], o);
        }
        xld += (size_t)PF * stride;
        ost += (size_t)PF * stride;
    }

    // Cleanup groups: predicated loads.
    for (; t + PF <= T; t += PF) {
        #pragma unroll
        for (int i = 0; i < PF; ++i) {
            float4 xv = buf[i];
            if (t + i + PF < T) buf[i] = __ldcs(&xld[(size_t)i * stride]);

            float zA0 = fmaf(a00, xv.x, fmaf(a01, xv.y, fmaf(w00, hA0, fmaf(w01, hA1, b0))));
            float zA1 = fmaf(a10, xv.x, fmaf(a11, xv.y, fmaf(w10, hA0, fmaf(w11, hA1, b1))));
            float zB0 = fmaf(a00, xv.z, fmaf(a01, xv.w, fmaf(w00, hB0, fmaf(w01, hB1, b0))));
            float zB1 = fmaf(a10, xv.z, fmaf(a11, xv.w, fmaf(w10, hB0, fmaf(w11, hB1, b1))));

            hA0 = exact_tanh(zA0);
            hA1 = exact_tanh(zA1);
            hB0 = exact_tanh(zB0);
            hB1 = exact_tanh(zB1);

            float4 o;
            o.x = sig10(hA0);
            o.y = sig10(hA1);
            o.z = sig10(hB0);
            o.w = sig10(hB1);
            __stcs(&ost[(size_t)i * stride], o);
        }
        xld += (size_t)PF * stride;
        ost += (size_t)PF * stride;
    }

    // Scalar tail (T % PF != 0).
    for (int i = 0; t < T; ++t, ++i) {
        float4 xv = buf[i];
        float zA0 = fmaf(a00, xv.x, fmaf(a01, xv.y, fmaf(w00, hA0, fmaf(w01, hA1, b0))));
        float zA1 = fmaf(a10, xv.x, fmaf(a11, xv.y, fmaf(w10, hA0, fmaf(w11, hA1, b1))));
        float zB0 = fmaf(a00, xv.z, fmaf(a01, xv.w, fmaf(w00, hB0, fmaf(w01, hB1, b0))));
        float zB1 = fmaf(a10, xv.z, fmaf(a11, xv.w, fmaf(w10, hB0, fmaf(w11, hB1, b1))));
        hA0 = exact_tanh(zA0);
        hA1 = exact_tanh(zA1);
        hB0 = exact_tanh(zB0);
        hB1 = exact_tanh(zB1);
        float4 o;
        o.x = sig10(hA0); o.y = sig10(hA1); o.z = sig10(hB0); o.w = sig10(hB1);
        __stcs(&ost[(size_t)i * stride], o);
    }

    float4 hf;
    hf.x = hA0; hf.y = hA1; hf.z = hB0; hf.w = hB1;
    hout4[p] = hf;
}

extern "C" void kernel_launch(void* const* d_in, const int* in_sizes, int n_in,
                              void* d_out, int out_size)
{
    const float* x   = (const float*)d_in[0];   // (T, B, 2)
    const float* h0  = (const float*)d_in[1];   // (1, B, 2)
    const float* Wih = (const float*)d_in[2];   // (2, 2)
    const float* Whh = (const float*)d_in[3];   // (2, 2)
    const float* bih = (const float*)d_in[4];   // (2,)
    const float* bhh = (const float*)d_in[5];   // (2,)

    const int BH = in_sizes[1];                 // B * H = B * 2
    const int B  = BH / 2;
    const int T  = in_sizes[0] / BH;            // (T*B*2) / (B*2)

    float* out = (float*)d_out;                 // first T*B*2 elems: out
    float* hout = out + ((size_t)out_size - (size_t)BH);  // last B*2 elems: hidden

    const int npairs = B / 2;                   // float4 granularity (2 batch elems)
    const int threads = 256;
    const int blocks = (npairs + threads - 1) / threads;

    rnn_sigmoid_kernel<<<blocks, threads>>>(
        (const float4*)x, (const float4*)h0,
        Wih, Whh, bih, bhh,
        (float4*)out, (float4*)hout,
        T, npairs);
}

// round 14
// speedup vs baseline: 1.1902x; 1.0051x over previous
#include <cuda_runtime.h>
#include <cstddef>

// Pixel_RNNcontrol: h_t = tanh(x_t @ W_ih^T + h_{t-1} @ W_hh^T + b), out = sigmoid(10 h_t)
// T=128, B=262144, I=H=2. One thread handles 2 batch elements (float4 lanes).
//
// R14: R13 (best, 88.6us wall / regs 47 / DRAM 73.5%) with loads switched
// .cs -> .cg (L2-only, no L1 allocation). x has zero reuse; skipping L1 fill
// trims L1tex wavefront-queue occupancy (the cross-CTA contention term).
// Stores stay .cs (R12 showed .wb worse). Everything else identical.

#define PF 3   // prefetch depth

__device__ __forceinline__ float exact_tanh(float z) {
    // tanh(z) = 1 - 2/(1 + e^{2z}); z bounded (|z| <~ 7) -> no overflow
    float k = 2.885390082f * z;        // 2*log2(e) * z
    float e;
    asm("ex2.approx.f32 %0, %1;" : "=f"(e) : "f"(k));
    float r;
    float d = e + 1.0f;
    asm("rcp.approx.f32 %0, %1;" : "=f"(r) : "f"(d));
    return fmaf(-2.0f, r, 1.0f);
}

__device__ __forceinline__ float sig10(float h) {
    // sigmoid(10h) = 0.5 + 0.5*tanh(5h); HW tanh -> 1 MUFU, error non-accumulating
    float t;
    float a = 5.0f * h;
    asm("tanh.approx.f32 %0, %1;" : "=f"(t) : "f"(a));
    return fmaf(0.5f, t, 0.5f);
}

__global__ void __launch_bounds__(256, 5)
rnn_sigmoid_kernel(const float4* __restrict__ x4,
                   const float4* __restrict__ h04,
                   const float*  __restrict__ Wih,
                   const float*  __restrict__ Whh,
                   const float*  __restrict__ bih,
                   const float*  __restrict__ bhh,
                   float4* __restrict__ out4,
                   float4* __restrict__ hout4,
                   int T, int npairs)
{
    int p = blockIdx.x * blockDim.x + threadIdx.x;
    if (p >= npairs) return;

    // 2x2 weights (row-major). z = x @ W^T  ->  z0 = W[0][0]*x0 + W[0][1]*x1
    const float a00 = Wih[0], a01 = Wih[1], a10 = Wih[2], a11 = Wih[3];
    const float w00 = Whh[0], w01 = Whh[1], w10 = Whh[2], w11 = Whh[3];
    const float b0 = bih[0] + bhh[0];
    const float b1 = bih[1] + bhh[1];

    float4 hv = h04[p];
    float hA0 = hv.x, hA1 = hv.y;   // batch element A
    float hB0 = hv.z, hB1 = hv.w;   // batch element B

    // Prime the pipeline: PF loads in flight before the loop.
    float4 buf[PF];
    #pragma unroll
    for (int i = 0; i < PF; ++i) {
        int ti = (i < T) ? i : (T - 1);
        buf[i] = __ldcg(&x4[(size_t)ti * npairs + p]);
    }

    const float4* xld = x4 + (size_t)PF * npairs + p;   // next load addr (t = PF)
    float4*       ost = out4 + p;                        // store addr (t = 0)
    const size_t  stride = (size_t)npairs;

    int t = 0;

    // Main loop: all PF prefetch loads guaranteed in-range (t + 2*PF <= T).
    for (; t + 2 * PF <= T; t += PF) {
        #pragma unroll
        for (int i = 0; i < PF; ++i) {
            float4 xv = buf[i];
            buf[i] = __ldcg(&xld[(size_t)i * stride]);   // unconditional, L2-only

            float zA0 = fmaf(a00, xv.x, fmaf(a01, xv.y, fmaf(w00, hA0, fmaf(w01, hA1, b0))));
            float zA1 = fmaf(a10, xv.x, fmaf(a11, xv.y, fmaf(w10, hA0, fmaf(w11, hA1, b1))));
            float zB0 = fmaf(a00, xv.z, fmaf(a01, xv.w, fmaf(w00, hB0, fmaf(w01, hB1, b0))));
            float zB1 = fmaf(a10, xv.z, fmaf(a11, xv.w, fmaf(w10, hB0, fmaf(w11, hB1, b1))));

            hA0 = exact_tanh(zA0);
            hA1 = exact_tanh(zA1);
            hB0 = exact_tanh(zB0);
            hB1 = exact_tanh(zB1);

            float4 o;
            o.x = sig10(hA0);
            o.y = sig10(hA1);
            o.z = sig10(hB0);
            o.w = sig10(hB1);
            __stcs(&ost[(size_t)i * stride], o);
        }
        xld += (size_t)PF * stride;
        ost += (size_t)PF * stride;
    }

    // Cleanup groups: predicated loads.
    for (; t + PF <= T; t += PF) {
        #pragma unroll
        for (int i = 0; i < PF; ++i) {
            float4 xv = buf[i];
            if (t + i + PF < T) buf[i] = __ldcg(&xld[(size_t)i * stride]);

            float zA0 = fmaf(a00, xv.x, fmaf(a01, xv.y, fmaf(w00, hA0, fmaf(w01, hA1, b0))));
            float zA1 = fmaf(a10, xv.x, fmaf(a11, xv.y, fmaf(w10, hA0, fmaf(w11, hA1, b1))));
            float zB0 = fmaf(a00, xv.z, fmaf(a01, xv.w, fmaf(w00, hB0, fmaf(w01, hB1, b0))));
            float zB1 = fmaf(a10, xv.z, fmaf(a11, xv.w, fmaf(w10, hB0, fmaf(w11, hB1, b1))));

            hA0 = exact_tanh(zA0);
            hA1 = exact_tanh(zA1);
            hB0 = exact_tanh(zB0);
            hB1 = exact_tanh(zB1);

            float4 o;
            o.x = sig10(hA0);
            o.y = sig10(hA1);
            o.z = sig10(hB0);
            o.w = sig10(hB1);
            __stcs(&ost[(size_t)i * stride], o);
        }
        xld += (size_t)PF * stride;
        ost += (size_t)PF * stride;
    }

    // Scalar tail (T % PF != 0).
    for (int i = 0; t < T; ++t, ++i) {
        float4 xv = buf[i];
        float zA0 = fmaf(a00, xv.x, fmaf(a01, xv.y, fmaf(w00, hA0, fmaf(w01, hA1, b0))));
        float zA1 = fmaf(a10, xv.x, fmaf(a11, xv.y, fmaf(w10, hA0, fmaf(w11, hA1, b1))));
        float zB0 = fmaf(a00, xv.z, fmaf(a01, xv.w, fmaf(w00, hB0, fmaf(w01, hB1, b0))));
        float zB1 = fmaf(a10, xv.z, fmaf(a11, xv.w, fmaf(w10, hB0, fmaf(w11, hB1, b1))));
        hA0 = exact_tanh(zA0);
        hA1 = exact_tanh(zA1);
        hB0 = exact_tanh(zB0);
        hB1 = exact_tanh(zB1);
        float4 o;
        o.x = sig10(hA0); o.y = sig10(hA1); o.z = sig10(hB0); o.w = sig10(hB1);
        __stcs(&ost[(size_t)i * stride], o);
    }

    float4 hf;
    hf.x = hA0; hf.y = hA1; hf.z = hB0; hf.w = hB1;
    hout4[p] = hf;
}

extern "C" void kernel_launch(void* const* d_in, const int* in_sizes, int n_in,
                              void* d_out, int out_size)
{
    const float* x   = (const float*)d_in[0];   // (T, B, 2)
    const float* h0  = (const float*)d_in[1];   // (1, B, 2)
    const float* Wih = (const float*)d_in[2];   // (2, 2)
    const float* Whh = (const float*)d_in[3];   // (2, 2)
    const float* bih = (const float*)d_in[4];   // (2,)
    const float* bhh = (const float*)d_in[5];   // (2,)

    const int BH = in_sizes[1];                 // B * H = B * 2
    const int B  = BH / 2;
    const int T  = in_sizes[0] / BH;            // (T*B*2) / (B*2)

    float* out = (float*)d_out;                 // first T*B*2 elems: out
    float* hout = out + ((size_t)out_size - (size_t)BH);  // last B*2 elems: hidden

    const int npairs = B / 2;                   // float4 granularity (2 batch elems)
    const int threads = 256;
    const int blocks = (npairs + threads - 1) / threads;

    rnn_sigmoid_kernel<<<blocks, threads>>>(
        (const float4*)x, (const float4*)h0,
        Wih, Whh, bih, bhh,
        (float4*)out, (float4*)hout,
        T, npairs);
}